// round 1
// baseline (speedup 1.0000x reference)
#include <cuda_runtime.h>
#include <math_constants.h>

#define Bq 8
#define Cq 64
#define CIq 32
#define Nq 2304          // 48*48
#define NP1 2305
#define NSORT 4096
#define TILES 36         // 2304/64
#define NBLK (Bq*TILES)  // 288

// ---------------- scratch (__device__ globals; no allocations) ----------------
__device__ float s_a[Bq*Nq];
__device__ float s_b[Bq*Nq];
__device__ float s_gx[Bq*Nq*CIq];          // [b][n][i]
__device__ float s_keys[Bq*Nq];            // sorted b ascending
__device__ int   s_perm[Bq*Nq];
__device__ float s_Sg[Bq*NP1*CIq];         // inclusive suffix sums, [b][k][i]
__device__ float s_Sbg[Bq*NP1*CIq];
__device__ float s_wy[Bq*Cq*Nq];           // pre-BN output, [b][c][n]
__device__ float s_part[NBLK*Cq*2];        // per-block (sum, sumsq) centered at W_b
__device__ float s_wa[Cq], s_wb[Cq], s_const[2];
__device__ float s_scale[Cq], s_shift[Cq];

// ---------------- K0: fold cp into theta/phi projections ----------------
__global__ void k0_precompute(const float* th_w, const float* th_b,
                              const float* ph_w, const float* ph_b,
                              const float* cp_wt, const float* cp_wp) {
    int c = threadIdx.x;          // 64 threads
    float sa = 0.f, sb = 0.f;
    #pragma unroll
    for (int i = 0; i < CIq; i++) {
        sa = fmaf(cp_wt[i], th_w[i*Cq + c], sa);
        sb = fmaf(cp_wp[i], ph_w[i*Cq + c], sb);
    }
    s_wa[c] = sa; s_wb[c] = sb;
    if (c == 0) {
        float ca = 0.f, cb = 0.f;
        #pragma unroll
        for (int i = 0; i < CIq; i++) {
            ca = fmaf(cp_wt[i], th_b[i], ca);
            cb = fmaf(cp_wp[i], ph_b[i], cb);
        }
        s_const[0] = ca; s_const[1] = cb;
    }
}

// ---------------- K1: per-position g_x, a, b ----------------
__global__ __launch_bounds__(256) void k1_project(const float* __restrict__ x,
                                                  const float* __restrict__ g_w,
                                                  const float* __restrict__ g_b) {
    __shared__ float xs[Cq*65];     // [c][pos], padded
    __shared__ float gws[CIq*65];   // [i][c], padded
    __shared__ float was[Cq], wbs[Cq], gbs[CIq], csts[2];
    int b = blockIdx.y, n0 = blockIdx.x * 64;
    int t = threadIdx.x;

    for (int idx = t; idx < Cq*64; idx += 256) {
        int c = idx >> 6, j = idx & 63;
        xs[c*65 + j] = x[(b*Cq + c)*Nq + n0 + j];
    }
    for (int idx = t; idx < CIq*Cq; idx += 256) {
        int i = idx >> 6, c = idx & 63;
        gws[i*65 + c] = g_w[idx];
    }
    if (t < Cq) { was[t] = s_wa[t]; wbs[t] = s_wb[t]; }
    if (t < CIq) gbs[t] = g_b[t];
    if (t < 2) csts[t] = s_const[t];
    __syncthreads();

    int i = t & 31, pg = t >> 5;
    #pragma unroll
    for (int p = 0; p < 8; p++) {
        int pos = pg*8 + p;
        float acc = gbs[i];
        #pragma unroll
        for (int c = 0; c < Cq; c++)
            acc = fmaf(gws[i*65 + c], xs[c*65 + pos], acc);
        s_gx[(b*Nq + n0 + pos)*CIq + i] = acc;
    }
    if (t < 64) {
        int j = t;
        float aa = csts[0], bb = csts[1];
        #pragma unroll
        for (int c = 0; c < Cq; c++) {
            float xv = xs[c*65 + j];
            aa = fmaf(was[c], xv, aa);
            bb = fmaf(wbs[c], xv, bb);
        }
        s_a[b*Nq + n0 + j] = aa;
        s_b[b*Nq + n0 + j] = bb;
    }
}

// ---------------- K2: per-batch bitonic sort of b (ascending) ----------------
__global__ __launch_bounds__(1024) void k2_sort() {
    __shared__ float key[NSORT];
    __shared__ int   val[NSORT];
    int b = blockIdx.x, t = threadIdx.x;
    for (int idx = t; idx < NSORT; idx += 1024) {
        key[idx] = (idx < Nq) ? s_b[b*Nq + idx] : CUDART_INF_F;
        val[idx] = idx;
    }
    __syncthreads();
    for (int k = 2; k <= NSORT; k <<= 1) {
        for (int j = k >> 1; j > 0; j >>= 1) {
            #pragma unroll
            for (int base = 0; base < NSORT; base += 1024) {
                int i = base + t;
                int ixj = i ^ j;
                if (ixj > i) {
                    bool up = ((i & k) == 0);
                    float ki = key[i], kj = key[ixj];
                    if ((ki > kj) == up) {
                        key[i] = kj; key[ixj] = ki;
                        int v = val[i]; val[i] = val[ixj]; val[ixj] = v;
                    }
                }
            }
            __syncthreads();
        }
    }
    for (int idx = t; idx < Nq; idx += 1024) {
        s_keys[b*Nq + idx] = key[idx];
        s_perm[b*Nq + idx] = val[idx];
    }
}

// ---------------- K4: suffix sums Sg, Sbg over sorted order ----------------
__global__ __launch_bounds__(1024) void k4_scan() {
    __shared__ int   perm_sm[Nq];
    __shared__ float key_sm[Nq];
    __shared__ float tot_g[32*32], tot_bg[32*32];   // [warp][i]
    int b = blockIdx.x, t = threadIdx.x;
    int w = t >> 5, lane = t & 31;
    for (int idx = t; idx < Nq; idx += 1024) {
        perm_sm[idx] = s_perm[b*Nq + idx];
        key_sm[idx]  = s_keys[b*Nq + idx];
    }
    __syncthreads();

    const int CH = Nq / 32;           // 72
    int k0 = w * CH, k1 = k0 + CH;
    const float* gxb = s_gx + b*Nq*CIq;

    float ag = 0.f, abg = 0.f;
    for (int k = k1 - 1; k >= k0; k--) {
        float g = gxb[perm_sm[k]*CIq + lane];
        ag += g;
        abg = fmaf(key_sm[k], g, abg);
    }
    tot_g[w*32 + lane] = ag;
    tot_bg[w*32 + lane] = abg;
    __syncthreads();

    float cg = 0.f, cbg = 0.f;
    for (int w2 = w + 1; w2 < 32; w2++) {
        cg  += tot_g[w2*32 + lane];
        cbg += tot_bg[w2*32 + lane];
    }
    if (w == 0) {   // Sg[N] = 0 (empty suffix)
        s_Sg [(b*NP1 + Nq)*CIq + lane] = 0.f;
        s_Sbg[(b*NP1 + Nq)*CIq + lane] = 0.f;
    }
    float ag2 = cg, abg2 = cbg;
    float* Sgb  = s_Sg  + b*NP1*CIq;
    float* Sbgb = s_Sbg + b*NP1*CIq;
    for (int k = k1 - 1; k >= k0; k--) {
        float g = gxb[perm_sm[k]*CIq + lane];
        ag2 += g;
        abg2 = fmaf(key_sm[k], g, abg2);
        Sgb [k*CIq + lane] = ag2;
        Sbgb[k*CIq + lane] = abg2;
    }
}

// ---------------- K5: y via threshold lookup, W projection, BN partials ----------------
__global__ __launch_bounds__(256) void k5_output(const float* __restrict__ Ww,
                                                 const float* __restrict__ Wb) {
    __shared__ float ws[Cq*33];     // W_w [c][i]
    __shared__ float ys[64*33];     // y [pos][i]
    __shared__ float wys[Cq*65];    // wy [c][pos]
    __shared__ float a_sm[64];
    __shared__ int   k_sm[64];
    __shared__ float psum[4*Cq], psumsq[4*Cq];

    int b = blockIdx.y, n0 = blockIdx.x * 64;
    int t = threadIdx.x;

    for (int idx = t; idx < Cq*CIq; idx += 256)
        ws[(idx >> 5)*33 + (idx & 31)] = Ww[idx];

    if (t < 64) {
        float a = s_a[b*Nq + n0 + t];
        float thr = -a;
        const float* keys = s_keys + b*Nq;
        int lo = 0, hi = Nq;
        while (lo < hi) {
            int mid = (lo + hi) >> 1;
            if (keys[mid] <= thr) lo = mid + 1; else hi = mid;
        }
        a_sm[t] = a; k_sm[t] = lo;
    }
    __syncthreads();

    // phase 1: y[pos][i]
    {
        int i = t & 31, pg = t >> 5;
        #pragma unroll
        for (int p = 0; p < 8; p++) {
            int pos = pg*8 + p;
            int k = k_sm[pos];
            float sg  = s_Sg [(b*NP1 + k)*CIq + i];
            float sbg = s_Sbg[(b*NP1 + k)*CIq + i];
            ys[pos*33 + i] = (fmaf(a_sm[pos], sg, sbg)) * (1.0f / (float)Nq);
        }
    }
    __syncthreads();

    // phase 2: wy[c][pos] and stats centered at W_b[c]
    {
        int c = t & 63, sub = t >> 6;
        float wbc = Wb[c];
        float ls = 0.f, ls2 = 0.f;
        for (int q = 0; q < 16; q++) {
            int pos = sub*16 + q;
            float acc = 0.f;
            #pragma unroll
            for (int i = 0; i < CIq; i++)
                acc = fmaf(ws[c*33 + i], ys[pos*33 + i], acc);
            wys[c*65 + pos] = acc + wbc;
            ls += acc; ls2 = fmaf(acc, acc, ls2);
        }
        psum[sub*Cq + c] = ls; psumsq[sub*Cq + c] = ls2;
    }
    __syncthreads();

    // coalesced global write of wy tile
    for (int base = 0; base < Cq; base += 4) {
        int cc = base + (t >> 6), j = t & 63;
        s_wy[(b*Cq + cc)*Nq + n0 + j] = wys[cc*65 + j];
    }
    if (t < Cq) {
        float s  = psum[t]   + psum[Cq+t]   + psum[2*Cq+t]   + psum[3*Cq+t];
        float s2 = psumsq[t] + psumsq[Cq+t] + psumsq[2*Cq+t] + psumsq[3*Cq+t];
        int blk = blockIdx.y * gridDim.x + blockIdx.x;
        s_part[(blk*Cq + t)*2 + 0] = s;
        s_part[(blk*Cq + t)*2 + 1] = s2;
    }
}

// ---------------- K6: finalize BN scale/shift ----------------
__global__ void k6_stats(const float* bn_g, const float* bn_b, const float* Wb) {
    int c = threadIdx.x;     // 64
    float s = 0.f, s2 = 0.f;
    for (int blk = 0; blk < NBLK; blk++) {
        s  += s_part[(blk*Cq + c)*2 + 0];
        s2 += s_part[(blk*Cq + c)*2 + 1];
    }
    const float M = (float)(Bq * Nq);
    float mv = s / M;                       // mean of (wy - Wb)
    float var = s2 / M - mv * mv;           // population var (shift-invariant)
    float mean = Wb[c] + mv;
    float scale = bn_g[c] * rsqrtf(var + 1e-5f);
    s_scale[c] = scale;
    s_shift[c] = bn_b[c] - mean * scale;
}

// ---------------- K7: normalize + residual ----------------
__global__ __launch_bounds__(256) void k7_final(const float* __restrict__ x,
                                                float* __restrict__ out) {
    int idx = blockIdx.x * blockDim.x + threadIdx.x;
    if (idx < Bq*Cq*Nq) {
        int c = (idx / Nq) & 63;
        out[idx] = fmaf(s_wy[idx], s_scale[c], s_shift[c]) + x[idx];
    }
}

// ---------------- launch ----------------
extern "C" void kernel_launch(void* const* d_in, const int* in_sizes, int n_in,
                              void* d_out, int out_size) {
    const float* x     = (const float*)d_in[0];
    const float* g_w   = (const float*)d_in[1];
    const float* g_b   = (const float*)d_in[2];
    const float* th_w  = (const float*)d_in[3];
    const float* th_b  = (const float*)d_in[4];
    const float* ph_w  = (const float*)d_in[5];
    const float* ph_b  = (const float*)d_in[6];
    const float* cp_wt = (const float*)d_in[7];
    const float* cp_wp = (const float*)d_in[8];
    const float* W_w   = (const float*)d_in[9];
    const float* W_b   = (const float*)d_in[10];
    const float* bn_g  = (const float*)d_in[11];
    const float* bn_b  = (const float*)d_in[12];
    float* out = (float*)d_out;

    k0_precompute<<<1, 64>>>(th_w, th_b, ph_w, ph_b, cp_wt, cp_wp);
    k1_project<<<dim3(TILES, Bq), 256>>>(x, g_w, g_b);
    k2_sort<<<Bq, 1024>>>();
    k4_scan<<<Bq, 1024>>>();
    k5_output<<<dim3(TILES, Bq), 256>>>(W_w, W_b);
    k6_stats<<<1, 64>>>(bn_g, bn_b, W_b);
    k7_final<<<(Bq*Cq*Nq + 255) / 256, 256>>>(x, out);
}

// round 2
// speedup vs baseline: 1.1828x; 1.1828x over previous
#include <cuda_runtime.h>
#include <math_constants.h>

#define Bq 8
#define Cq 64
#define CIq 32
#define Nq 2304          // 48*48
#define NP1 2305
#define TILES 36         // 2304/64
#define NBLK (Bq*TILES)  // 288
#define NCH 72           // suffix-scan chunks per batch
#define CHSZ 32          // elements per chunk (72*32 = 2304)

// ---------------- scratch (__device__ globals; no allocations) ----------------
__device__ float s_a[Bq*Nq];
__device__ float s_b[Bq*Nq];
__device__ float s_gx[Bq*Nq*CIq];          // [b][n][i]
__device__ float s_keys[Bq*Nq];            // sorted b ascending (stable by index)
__device__ int   s_perm[Bq*Nq];
__device__ int   s_kstar[Bq*Nq];           // per-position threshold rank
__device__ float s_ctg[Bq*NCH*CIq];        // chunk totals (g)
__device__ float s_ctbg[Bq*NCH*CIq];       // chunk totals (b*g)
__device__ float s_cag[Bq*NCH*CIq];        // exclusive chunk carries
__device__ float s_cabg[Bq*NCH*CIq];
__device__ float s_Sg[Bq*NP1*CIq];         // inclusive suffix sums, [b][k][i]
__device__ float s_Sbg[Bq*NP1*CIq];
__device__ float s_wy[Bq*Cq*Nq];           // pre-BN output, [b][c][n]
__device__ float s_part[NBLK*Cq*2];        // per-block (sum, sumsq) centered at W_b
__device__ float s_wa[Cq], s_wb[Cq], s_const[2];
__device__ float s_scale[Cq], s_shift[Cq];

// ---------------- KA: fold cp into theta/phi projections ----------------
__global__ void ka_precompute(const float* th_w, const float* th_b,
                              const float* ph_w, const float* ph_b,
                              const float* cp_wt, const float* cp_wp) {
    int c = threadIdx.x;          // 64 threads
    float sa = 0.f, sb = 0.f;
    #pragma unroll
    for (int i = 0; i < CIq; i++) {
        sa = fmaf(cp_wt[i], th_w[i*Cq + c], sa);
        sb = fmaf(cp_wp[i], ph_w[i*Cq + c], sb);
    }
    s_wa[c] = sa; s_wb[c] = sb;
    if (c == 0) {
        float ca = 0.f, cb = 0.f;
        #pragma unroll
        for (int i = 0; i < CIq; i++) {
            ca = fmaf(cp_wt[i], th_b[i], ca);
            cb = fmaf(cp_wp[i], ph_b[i], cb);
        }
        s_const[0] = ca; s_const[1] = cb;
    }
}

// ---------------- K1: per-position g_x, a, b ----------------
__global__ __launch_bounds__(256) void k1_project(const float* __restrict__ x,
                                                  const float* __restrict__ g_w,
                                                  const float* __restrict__ g_b) {
    __shared__ float xs[Cq*68];     // [c][pos], pad 68 (16B-aligned rows)
    __shared__ float gws[CIq*65];   // [i][c], padded
    __shared__ float was[Cq], wbs[Cq], gbs[CIq], csts[2];
    int b = blockIdx.y, n0 = blockIdx.x * 64;
    int t = threadIdx.x;

    for (int idx = t; idx < Cq*64; idx += 256) {
        int c = idx >> 6, j = idx & 63;
        xs[c*68 + j] = x[(b*Cq + c)*Nq + n0 + j];
    }
    for (int idx = t; idx < CIq*Cq; idx += 256) {
        int i = idx >> 6, c = idx & 63;
        gws[i*65 + c] = g_w[idx];
    }
    if (t < Cq) { was[t] = s_wa[t]; wbs[t] = s_wb[t]; }
    if (t < CIq) gbs[t] = g_b[t];
    if (t < 2) csts[t] = s_const[t];
    __syncthreads();

    int i = t & 31, pg = t >> 5;
    float wrow[Cq];
    #pragma unroll
    for (int c = 0; c < Cq; c++) wrow[c] = gws[i*65 + c];

    float acc[8];
    #pragma unroll
    for (int p = 0; p < 8; p++) acc[p] = gbs[i];

    #pragma unroll
    for (int c = 0; c < Cq; c++) {
        float4 xa = *(const float4*)&xs[c*68 + pg*8];
        float4 xb = *(const float4*)&xs[c*68 + pg*8 + 4];
        float w = wrow[c];
        acc[0] = fmaf(w, xa.x, acc[0]); acc[1] = fmaf(w, xa.y, acc[1]);
        acc[2] = fmaf(w, xa.z, acc[2]); acc[3] = fmaf(w, xa.w, acc[3]);
        acc[4] = fmaf(w, xb.x, acc[4]); acc[5] = fmaf(w, xb.y, acc[5]);
        acc[6] = fmaf(w, xb.z, acc[6]); acc[7] = fmaf(w, xb.w, acc[7]);
    }
    #pragma unroll
    for (int p = 0; p < 8; p++)
        s_gx[(b*Nq + n0 + pg*8 + p)*CIq + i] = acc[p];

    if (t < 64) {
        int j = t;
        float aa = csts[0], bb = csts[1];
        #pragma unroll
        for (int c = 0; c < Cq; c++) {
            float xv = xs[c*68 + j];
            aa = fmaf(was[c], xv, aa);
            bb = fmaf(wbs[c], xv, bb);
        }
        s_a[b*Nq + n0 + j] = aa;
        s_b[b*Nq + n0 + j] = bb;
    }
}

// ---------------- KR: stable rank by counting -> sorted keys + perm ----------------
__global__ __launch_bounds__(128) void kr_rank() {
    __shared__ float sb[Nq];        // 9.2 KB
    int b = blockIdx.y;
    int t = threadIdx.x;
    int m = blockIdx.x * 128 + t;
    const float* bb = s_b + b*Nq;
    for (int idx = t; idx < Nq; idx += 128) sb[idx] = bb[idx];
    __syncthreads();

    const float4* sb4 = (const float4*)sb;
    float bm = sb[m];
    int mq = m >> 2;
    int c0 = 0, c1 = 0, c2 = 0, c3 = 0;
    // j < m region (except boundary vec): stable tie-break via <=
    for (int q = 0; q < mq; q++) {
        float4 v = sb4[q];
        c0 += (v.x <= bm); c1 += (v.y <= bm);
        c2 += (v.z <= bm); c3 += (v.w <= bm);
    }
    { // boundary float4 containing m
        float4 v = sb4[mq];
        int jb = mq << 2;
        c0 += (jb + 0 < m) ? (v.x <= bm) : (v.x < bm);
        c1 += (jb + 1 < m) ? (v.y <= bm) : (v.y < bm);
        c2 += (jb + 2 < m) ? (v.z <= bm) : (v.z < bm);
        c3 += (jb + 3 < m) ? (v.w <= bm) : (v.w < bm);
    }
    // j > m region: strict <
    for (int q = mq + 1; q < Nq/4; q++) {
        float4 v = sb4[q];
        c0 += (v.x < bm); c1 += (v.y < bm);
        c2 += (v.z < bm); c3 += (v.w < bm);
    }
    int rank = c0 + c1 + c2 + c3;
    s_keys[b*Nq + rank] = bm;
    s_perm[b*Nq + rank] = m;
}

// ---------------- K4a: chunk totals + per-position threshold rank ----------------
__global__ __launch_bounds__(256) void k4a_totals() {
    __shared__ float keys_sm[Nq];
    int b = blockIdx.y, t = threadIdx.x;
    int w = t >> 5, lane = t & 31;
    for (int idx = t; idx < Nq; idx += 256)
        keys_sm[idx] = s_keys[b*Nq + idx];
    __syncthreads();

    // phase A: chunk totals (warp = chunk)
    {
        int chunk = blockIdx.x * 8 + w;        // 0..71
        int k0 = chunk * CHSZ;
        const float* gxb = s_gx + b*Nq*CIq;
        const int* permb = s_perm + b*Nq;
        float ag = 0.f, abg = 0.f;
        #pragma unroll
        for (int k = k0; k < k0 + CHSZ; k++) {
            int m = permb[k];                  // uniform load
            float g = gxb[m*CIq + lane];
            ag += g;
            abg = fmaf(keys_sm[k], g, abg);
        }
        s_ctg [(b*NCH + chunk)*CIq + lane] = ag;
        s_ctbg[(b*NCH + chunk)*CIq + lane] = abg;
    }

    // phase B: binary search threshold rank for 256 positions
    {
        int pos = blockIdx.x * 256 + t;        // 0..2303
        float thr = -s_a[b*Nq + pos];
        int lo = 0, hi = Nq;
        while (lo < hi) {
            int mid = (lo + hi) >> 1;
            if (keys_sm[mid] <= thr) lo = mid + 1; else hi = mid;
        }
        s_kstar[b*Nq + pos] = lo;
    }
}

// ---------------- K4b: exclusive suffix carries over chunks ----------------
__global__ __launch_bounds__(256) void k4b_carry() {
    int t = threadIdx.x;
    int b = t >> 5, lane = t & 31;   // warp = batch
    float rg = 0.f, rbg = 0.f;
    #pragma unroll 8
    for (int ch = NCH - 1; ch >= 0; ch--) {
        s_cag [(b*NCH + ch)*CIq + lane] = rg;
        s_cabg[(b*NCH + ch)*CIq + lane] = rbg;
        rg  += s_ctg [(b*NCH + ch)*CIq + lane];
        rbg += s_ctbg[(b*NCH + ch)*CIq + lane];
    }
    s_Sg [(b*NP1 + Nq)*CIq + lane] = 0.f;   // empty-suffix row
    s_Sbg[(b*NP1 + Nq)*CIq + lane] = 0.f;
}

// ---------------- K4c: write full suffix sums ----------------
__global__ __launch_bounds__(256) void k4c_write() {
    int b = blockIdx.y, t = threadIdx.x;
    int w = t >> 5, lane = t & 31;
    int chunk = blockIdx.x * 8 + w;
    int k0 = chunk * CHSZ;
    const float* gxb = s_gx + b*Nq*CIq;
    const int* permb = s_perm + b*Nq;
    const float* keyb = s_keys + b*Nq;
    float ag  = s_cag [(b*NCH + chunk)*CIq + lane];
    float abg = s_cabg[(b*NCH + chunk)*CIq + lane];
    #pragma unroll
    for (int k = k0 + CHSZ - 1; k >= k0; k--) {
        int m = permb[k];
        float g = gxb[m*CIq + lane];
        ag += g;
        abg = fmaf(keyb[k], g, abg);
        s_Sg [(b*NP1 + k)*CIq + lane] = ag;
        s_Sbg[(b*NP1 + k)*CIq + lane] = abg;
    }
}

// ---------------- K5: y lookup, W projection, BN partials ----------------
__global__ __launch_bounds__(256) void k5_output(const float* __restrict__ Ww,
                                                 const float* __restrict__ Wb) {
    __shared__ float ws[Cq*33];     // W_w [c][i]
    __shared__ float ys[64*36];     // y [pos][i], pad 36 (16B-aligned)
    __shared__ float wys[Cq*65];    // wy [c][pos]
    __shared__ float a_sm[64];
    __shared__ int   k_sm[64];
    __shared__ float psum[4*Cq], psumsq[4*Cq];

    int b = blockIdx.y, n0 = blockIdx.x * 64;
    int t = threadIdx.x;

    for (int idx = t; idx < Cq*CIq; idx += 256)
        ws[(idx >> 5)*33 + (idx & 31)] = Ww[idx];

    if (t < 64) {
        a_sm[t] = s_a[b*Nq + n0 + t];
        k_sm[t] = s_kstar[b*Nq + n0 + t];
    }
    __syncthreads();

    // phase 1: y[pos][i]
    {
        int i = t & 31, pg = t >> 5;
        #pragma unroll
        for (int p = 0; p < 8; p++) {
            int pos = pg*8 + p;
            int k = k_sm[pos];
            float sg  = s_Sg [(b*NP1 + k)*CIq + i];
            float sbg = s_Sbg[(b*NP1 + k)*CIq + i];
            ys[pos*36 + i] = fmaf(a_sm[pos], sg, sbg) * (1.0f / (float)Nq);
        }
    }
    __syncthreads();

    // phase 2: wy[c][pos] and stats centered at W_b[c]
    {
        int c = t & 63, sub = t >> 6;
        float wreg[CIq];
        #pragma unroll
        for (int i = 0; i < CIq; i++) wreg[i] = ws[c*33 + i];
        float wbc = Wb[c];
        float ls = 0.f, ls2 = 0.f;
        #pragma unroll
        for (int q = 0; q < 16; q++) {
            int pos = sub*16 + q;
            const float4* yv = (const float4*)&ys[pos*36];
            float acc = 0.f;
            #pragma unroll
            for (int i4 = 0; i4 < CIq/4; i4++) {
                float4 v = yv[i4];
                acc = fmaf(wreg[i4*4+0], v.x, acc);
                acc = fmaf(wreg[i4*4+1], v.y, acc);
                acc = fmaf(wreg[i4*4+2], v.z, acc);
                acc = fmaf(wreg[i4*4+3], v.w, acc);
            }
            wys[c*65 + pos] = acc + wbc;
            ls += acc; ls2 = fmaf(acc, acc, ls2);
        }
        psum[sub*Cq + c] = ls; psumsq[sub*Cq + c] = ls2;
    }
    __syncthreads();

    // coalesced global write of wy tile
    for (int base = 0; base < Cq; base += 4) {
        int cc = base + (t >> 6), j = t & 63;
        s_wy[(b*Cq + cc)*Nq + n0 + j] = wys[cc*65 + j];
    }
    if (t < Cq) {
        float s  = psum[t]   + psum[Cq+t]   + psum[2*Cq+t]   + psum[3*Cq+t];
        float s2 = psumsq[t] + psumsq[Cq+t] + psumsq[2*Cq+t] + psumsq[3*Cq+t];
        int blk = blockIdx.y * gridDim.x + blockIdx.x;
        s_part[(blk*Cq + t)*2 + 0] = s;
        s_part[(blk*Cq + t)*2 + 1] = s2;
    }
}

// ---------------- K6: finalize BN scale/shift ----------------
__global__ void k6_stats(const float* bn_g, const float* bn_b, const float* Wb) {
    int c = threadIdx.x;     // 64
    float s0 = 0.f, s1 = 0.f, q0 = 0.f, q1 = 0.f;
    #pragma unroll 4
    for (int blk = 0; blk < NBLK; blk += 2) {
        s0 += s_part[(blk*Cq + c)*2 + 0];
        q0 += s_part[(blk*Cq + c)*2 + 1];
        s1 += s_part[((blk+1)*Cq + c)*2 + 0];
        q1 += s_part[((blk+1)*Cq + c)*2 + 1];
    }
    float s = s0 + s1, s2 = q0 + q1;
    const float M = (float)(Bq * Nq);
    float mv = s / M;                       // mean of (wy - Wb)
    float var = s2 / M - mv * mv;           // population var (shift-invariant)
    float mean = Wb[c] + mv;
    float scale = bn_g[c] * rsqrtf(var + 1e-5f);
    s_scale[c] = scale;
    s_shift[c] = bn_b[c] - mean * scale;
}

// ---------------- K7: normalize + residual (float4) ----------------
__global__ __launch_bounds__(256) void k7_final(const float* __restrict__ x,
                                                float* __restrict__ out) {
    int i4 = blockIdx.x * blockDim.x + threadIdx.x;
    const int TOT4 = Bq*Cq*Nq/4;
    if (i4 < TOT4) {
        int e = i4 * 4;
        int c = (e / Nq) & 63;
        float sc = s_scale[c], sh = s_shift[c];
        float4 w = ((const float4*)s_wy)[i4];
        float4 xv = ((const float4*)x)[i4];
        float4 o;
        o.x = fmaf(w.x, sc, sh) + xv.x;
        o.y = fmaf(w.y, sc, sh) + xv.y;
        o.z = fmaf(w.z, sc, sh) + xv.z;
        o.w = fmaf(w.w, sc, sh) + xv.w;
        ((float4*)out)[i4] = o;
    }
}

// ---------------- launch ----------------
extern "C" void kernel_launch(void* const* d_in, const int* in_sizes, int n_in,
                              void* d_out, int out_size) {
    const float* x     = (const float*)d_in[0];
    const float* g_w   = (const float*)d_in[1];
    const float* g_b   = (const float*)d_in[2];
    const float* th_w  = (const float*)d_in[3];
    const float* th_b  = (const float*)d_in[4];
    const float* ph_w  = (const float*)d_in[5];
    const float* ph_b  = (const float*)d_in[6];
    const float* cp_wt = (const float*)d_in[7];
    const float* cp_wp = (const float*)d_in[8];
    const float* W_w   = (const float*)d_in[9];
    const float* W_b   = (const float*)d_in[10];
    const float* bn_g  = (const float*)d_in[11];
    const float* bn_b  = (const float*)d_in[12];
    float* out = (float*)d_out;

    ka_precompute<<<1, 64>>>(th_w, th_b, ph_w, ph_b, cp_wt, cp_wp);
    k1_project<<<dim3(TILES, Bq), 256>>>(x, g_w, g_b);
    kr_rank<<<dim3(Nq/128, Bq), 128>>>();
    k4a_totals<<<dim3(9, Bq), 256>>>();
    k4b_carry<<<1, 256>>>();
    k4c_write<<<dim3(9, Bq), 256>>>();
    k5_output<<<dim3(TILES, Bq), 256>>>(W_w, W_b);
    k6_stats<<<1, 64>>>(bn_g, bn_b, W_b);
    k7_final<<<(Bq*Cq*Nq/4 + 255) / 256, 256>>>(x, out);
}

// round 3
// speedup vs baseline: 1.6803x; 1.4205x over previous
#include <cuda_runtime.h>

#define Bq 8
#define Cq 64
#define CIq 32
#define Nq 2304          // 48*48
#define NP1 2305
#define TILES 36         // 2304/64
#define NTILE (Bq*TILES) // 288
#define NCH 72           // suffix-scan chunks per batch
#define CHSZ 32
#define GRID 148
#define NTHR 256

// ---------------- scratch (__device__ globals; no allocations) ----------------
__device__ float s_a[Bq*Nq];
__device__ float s_b[Bq*Nq];
__device__ float s_gx[Bq*Nq*CIq];          // [b][n][i]
__device__ float s_keys[Bq*Nq];            // sorted b ascending (stable)
__device__ int   s_perm[Bq*Nq];
__device__ int   s_kstar[Bq*Nq];
__device__ float s_ctg[Bq*NCH*CIq];        // chunk totals (g)
__device__ float s_ctbg[Bq*NCH*CIq];       // chunk totals (b*g)
__device__ float s_Sg[Bq*NP1*CIq];         // inclusive suffix sums
__device__ float s_Sbg[Bq*NP1*CIq];
__device__ float s_wy[Bq*Cq*Nq];           // pre-BN output
__device__ float s_part[NTILE*Cq*2];       // per-tile (sum, sumsq)

// grid barrier state
__device__ unsigned g_bar = 0;
__device__ volatile unsigned g_gen = 0;

__device__ __forceinline__ void gsync() {
    __syncthreads();
    if (threadIdx.x == 0) {
        __threadfence();
        unsigned gen = g_gen;
        if (atomicAdd(&g_bar, 1u) == gridDim.x - 1) {
            g_bar = 0;
            __threadfence();
            g_gen = gen + 1;
        } else {
            while (g_gen == gen) { __nanosleep(64); }
        }
        __threadfence();
    }
    __syncthreads();
}

__global__ __launch_bounds__(NTHR, 1) void fused_nonlocal(
    const float* __restrict__ x,
    const float* __restrict__ g_w,  const float* __restrict__ g_b,
    const float* __restrict__ th_w, const float* __restrict__ th_b,
    const float* __restrict__ ph_w, const float* __restrict__ ph_b,
    const float* __restrict__ cp_wt, const float* __restrict__ cp_wp,
    const float* __restrict__ W_w,  const float* __restrict__ W_b,
    const float* __restrict__ bn_g, const float* __restrict__ bn_b,
    float* __restrict__ out)
{
    __shared__ __align__(16) unsigned char SM[37888];
    int t = threadIdx.x;

    // ================= P1: projections (gx, a, b); KA folded in =================
    {
        float* xs  = (float*)SM;                      // 64*68 floats
        float* gws = (float*)(SM + 17408);            // 32*65
        float* was = (float*)(SM + 17408 + 8320);     // 64
        float* wbs = was + 64;                        // 64
        float* cst = wbs + 64;                        // 2 (+pad)
        float* gbs = cst + 4;                         // 32

        if (t < 64) {
            float sa = 0.f, sb = 0.f;
            #pragma unroll
            for (int i = 0; i < CIq; i++) {
                sa = fmaf(cp_wt[i], th_w[i*Cq + t], sa);
                sb = fmaf(cp_wp[i], ph_w[i*Cq + t], sb);
            }
            was[t] = sa; wbs[t] = sb;
        } else if (t == 64) {
            float ca = 0.f;
            #pragma unroll
            for (int i = 0; i < CIq; i++) ca = fmaf(cp_wt[i], th_b[i], ca);
            cst[0] = ca;
        } else if (t == 65) {
            float cb = 0.f;
            #pragma unroll
            for (int i = 0; i < CIq; i++) cb = fmaf(cp_wp[i], ph_b[i], cb);
            cst[1] = cb;
        }
        if (t >= 128 && t < 160) gbs[t - 128] = g_b[t - 128];
        for (int idx = t; idx < CIq*Cq; idx += NTHR)
            gws[(idx >> 6)*65 + (idx & 63)] = g_w[idx];
        __syncthreads();

        int i = t & 31, pg = t >> 5;
        float wrow[Cq];
        #pragma unroll
        for (int c = 0; c < Cq; c++) wrow[c] = gws[i*65 + c];
        float gb_i = gbs[i];
        float cst0 = cst[0], cst1 = cst[1];

        for (int tile = blockIdx.x; tile < NTILE; tile += GRID) {
            int b = tile / TILES, n0 = (tile % TILES)*64;
            float4* xs4 = (float4*)xs;
            const float4* xg = (const float4*)x;
            for (int idx = t; idx < Cq*16; idx += NTHR) {
                int c = idx >> 4, q = idx & 15;
                xs4[c*17 + q] = xg[(((b*Cq + c)*Nq + n0) >> 2) + q];
            }
            __syncthreads();

            float acc[8];
            #pragma unroll
            for (int p = 0; p < 8; p++) acc[p] = gb_i;
            #pragma unroll
            for (int c = 0; c < Cq; c++) {
                float4 xa = *(const float4*)&xs[c*68 + pg*8];
                float4 xb = *(const float4*)&xs[c*68 + pg*8 + 4];
                float w = wrow[c];
                acc[0] = fmaf(w, xa.x, acc[0]); acc[1] = fmaf(w, xa.y, acc[1]);
                acc[2] = fmaf(w, xa.z, acc[2]); acc[3] = fmaf(w, xa.w, acc[3]);
                acc[4] = fmaf(w, xb.x, acc[4]); acc[5] = fmaf(w, xb.y, acc[5]);
                acc[6] = fmaf(w, xb.z, acc[6]); acc[7] = fmaf(w, xb.w, acc[7]);
            }
            #pragma unroll
            for (int p = 0; p < 8; p++)
                s_gx[(b*Nq + n0 + pg*8 + p)*CIq + i] = acc[p];

            if (t < 64) {
                float aa = cst0, bb = cst1;
                #pragma unroll
                for (int c = 0; c < Cq; c++) {
                    float xv = xs[c*68 + t];
                    aa = fmaf(was[c], xv, aa);
                    bb = fmaf(wbs[c], xv, bb);
                }
                s_a[b*Nq + n0 + t] = aa;
                s_b[b*Nq + n0 + t] = bb;
            }
            __syncthreads();
        }
    }
    gsync();

    // ================= P2: stable rank-by-counting -> sorted keys + perm =========
    {
        unsigned* osb = (unsigned*)SM;                // 2304
        unsigned* cnt = (unsigned*)(SM + Nq*4);       // 4*128

        for (int item = blockIdx.x; item < 144; item += GRID) {
            int b = item / 18, slice = item % 18;
            int pos_base = slice * 128;
            for (int idx = t; idx < Nq; idx += NTHR) {
                int iv = __float_as_int(s_b[b*Nq + idx]);
                osb[idx] = (unsigned)(iv ^ ((iv >> 31) | 0x80000000));
            }
            __syncthreads();

            int g = t & 63, s = t >> 6;
            int m0 = pos_base + g, m1 = m0 + 64;
            unsigned om0 = osb[m0], om1 = osb[m1];
            int jlo = s * 576, jhi = jlo + 576;
            unsigned cnt0 = 0, cnt1 = 0;
            const uint4* o4 = (const uint4*)osb;

            auto count_range = [&](int lo, int hi, unsigned th0, unsigned th1) {
                int v0 = min((lo + 3) & ~3, hi);
                int v1 = max(hi & ~3, v0);
                for (int j = lo; j < v0; j++) {
                    unsigned v = osb[j]; cnt0 += (v < th0); cnt1 += (v < th1);
                }
                for (int q = v0 >> 2; q < (v1 >> 2); q++) {
                    uint4 v = o4[q];
                    cnt0 += (v.x < th0) + (v.y < th0) + (v.z < th0) + (v.w < th0);
                    cnt1 += (v.x < th1) + (v.y < th1) + (v.z < th1) + (v.w < th1);
                }
                for (int j = v1; j < hi; j++) {
                    unsigned v = osb[j]; cnt0 += (v < th0); cnt1 += (v < th1);
                }
            };
            // tie-break: j<m counts (v<=om) == (v < om+1); j>=m counts (v < om)
            int A  = min(max(m0, jlo), jhi);
            int Bp = min(max(m1, A), jhi);
            count_range(jlo, A,  om0 + 1u, om1 + 1u);
            count_range(A,   Bp, om0,      om1 + 1u);
            count_range(Bp,  jhi, om0,     om1);

            cnt[s*128 + g]      = cnt0;
            cnt[s*128 + 64 + g] = cnt1;
            __syncthreads();

            if (t < 128) {
                int pos = pos_base + t;
                unsigned rank = cnt[t] + cnt[128 + t] + cnt[256 + t] + cnt[384 + t];
                s_keys[b*Nq + rank] = s_b[b*Nq + pos];
                s_perm[b*Nq + rank] = pos;
            }
            __syncthreads();
        }
    }
    gsync();

    // ================= P3: chunk totals + per-position k* =======================
    {
        float* keys_sm = (float*)SM;                  // 2304
        for (int item = blockIdx.x; item < 144; item += GRID) {
            int b = item / 18, sub = item % 18;
            for (int idx = t; idx < Nq; idx += NTHR)
                keys_sm[idx] = s_keys[b*Nq + idx];
            __syncthreads();

            int w = t >> 5, lane = t & 31;
            if (w < 4) {
                int chunk = sub*4 + w;
                int k0 = chunk * CHSZ;
                const float* gxb = s_gx + b*Nq*CIq;
                const int* permb = s_perm + b*Nq;
                float ag = 0.f, abg = 0.f;
                #pragma unroll
                for (int k = k0; k < k0 + CHSZ; k++) {
                    int m = permb[k];
                    float gg = gxb[m*CIq + lane];
                    ag += gg;
                    abg = fmaf(keys_sm[k], gg, abg);
                }
                s_ctg [(b*NCH + chunk)*CIq + lane] = ag;
                s_ctbg[(b*NCH + chunk)*CIq + lane] = abg;
            }
            if (t < 128) {
                int pos = sub*128 + t;
                float thr = -s_a[b*Nq + pos];
                int lo = 0, hi = Nq;
                while (lo < hi) {
                    int mid = (lo + hi) >> 1;
                    if (keys_sm[mid] <= thr) lo = mid + 1; else hi = mid;
                }
                s_kstar[b*Nq + pos] = lo;
            }
            __syncthreads();
        }
    }
    gsync();

    // ================= P4: suffix sums (carry computed per-warp) =================
    {
        int w = t >> 5, lane = t & 31;
        for (int item = blockIdx.x; item < 72; item += GRID) {
            int b = item / 9, cb = item % 9;
            int chunk = cb*8 + w;
            float rg = 0.f, rbg = 0.f;
            #pragma unroll 4
            for (int ch = chunk + 1; ch < NCH; ch++) {
                rg  += s_ctg [(b*NCH + ch)*CIq + lane];
                rbg += s_ctbg[(b*NCH + ch)*CIq + lane];
            }
            int k0 = chunk * CHSZ;
            const float* gxb = s_gx + b*Nq*CIq;
            const int* permb = s_perm + b*Nq;
            const float* keyb = s_keys + b*Nq;
            float ag = rg, abg = rbg;
            #pragma unroll
            for (int k = k0 + CHSZ - 1; k >= k0; k--) {
                int m = permb[k];
                float gg = gxb[m*CIq + lane];
                ag += gg;
                abg = fmaf(keyb[k], gg, abg);
                s_Sg [(b*NP1 + k)*CIq + lane] = ag;
                s_Sbg[(b*NP1 + k)*CIq + lane] = abg;
            }
            if (cb == 0 && w == 0) {
                s_Sg [(b*NP1 + Nq)*CIq + lane] = 0.f;
                s_Sbg[(b*NP1 + Nq)*CIq + lane] = 0.f;
            }
        }
    }
    gsync();

    // ================= P5: y lookup + W projection + BN partials =================
    {
        float* ws   = (float*)SM;                       // 64*33
        float* ys   = (float*)(SM + 8448);              // 64*36
        float* wys  = (float*)(SM + 8448 + 9216);       // 64*65
        float* a_sm = (float*)(SM + 8448 + 9216 + 16640); // 64
        int*   k_sm = (int*)(a_sm + 64);                // 64
        float* psum = (float*)(k_sm + 64);              // 256
        float* psq  = psum + 256;                       // 256

        for (int idx = t; idx < Cq*CIq; idx += NTHR)
            ws[(idx >> 5)*33 + (idx & 31)] = W_w[idx];
        __syncthreads();

        int c = t & 63, sub = t >> 6;
        float wreg[CIq];
        #pragma unroll
        for (int i = 0; i < CIq; i++) wreg[i] = ws[c*33 + i];
        float wbc = W_b[c];

        for (int tile = blockIdx.x; tile < NTILE; tile += GRID) {
            int b = tile / TILES, n0 = (tile % TILES)*64;
            if (t < 64) {
                a_sm[t] = s_a[b*Nq + n0 + t];
                k_sm[t] = s_kstar[b*Nq + n0 + t];
            }
            __syncthreads();

            {
                int i = t & 31, pg = t >> 5;
                #pragma unroll
                for (int p = 0; p < 8; p++) {
                    int pos = pg*8 + p;
                    int k = k_sm[pos];
                    float sg  = s_Sg [(b*NP1 + k)*CIq + i];
                    float sbg = s_Sbg[(b*NP1 + k)*CIq + i];
                    ys[pos*36 + i] = fmaf(a_sm[pos], sg, sbg) * (1.0f / (float)Nq);
                }
            }
            __syncthreads();

            {
                float ls = 0.f, ls2 = 0.f;
                #pragma unroll
                for (int q = 0; q < 16; q++) {
                    int pos = sub*16 + q;
                    const float4* yv = (const float4*)&ys[pos*36];
                    float acc = 0.f;
                    #pragma unroll
                    for (int i4 = 0; i4 < CIq/4; i4++) {
                        float4 v = yv[i4];
                        acc = fmaf(wreg[i4*4+0], v.x, acc);
                        acc = fmaf(wreg[i4*4+1], v.y, acc);
                        acc = fmaf(wreg[i4*4+2], v.z, acc);
                        acc = fmaf(wreg[i4*4+3], v.w, acc);
                    }
                    wys[c*65 + pos] = acc + wbc;
                    ls += acc; ls2 = fmaf(acc, acc, ls2);
                }
                psum[sub*64 + c] = ls; psq[sub*64 + c] = ls2;
            }
            __syncthreads();

            for (int base = 0; base < Cq; base += 4) {
                int cc = base + (t >> 6), j = t & 63;
                s_wy[(b*Cq + cc)*Nq + n0 + j] = wys[cc*65 + j];
            }
            if (t < 64) {
                float s  = psum[t] + psum[64+t] + psum[128+t] + psum[192+t];
                float s2 = psq[t]  + psq[64+t]  + psq[128+t]  + psq[192+t];
                s_part[(tile*Cq + t)*2 + 0] = s;
                s_part[(tile*Cq + t)*2 + 1] = s2;
            }
            __syncthreads();
        }
    }
    gsync();

    // ================= P6: BN stats (redundant per block) + final ================
    {
        float* red   = (float*)SM;           // 2*4*64
        float* scale = (float*)(SM + 4096);  // 64
        float* shift = scale + 64;           // 64

        int c = t & 63, r = t >> 6;
        float s = 0.f, s2 = 0.f;
        for (int blk = r; blk < NTILE; blk += 4) {
            s  += s_part[(blk*Cq + c)*2 + 0];
            s2 += s_part[(blk*Cq + c)*2 + 1];
        }
        red[r*64 + c] = s;
        red[256 + r*64 + c] = s2;
        __syncthreads();
        if (t < 64) {
            float ss = red[t] + red[64+t] + red[128+t] + red[192+t];
            float qq = red[256+t] + red[320+t] + red[384+t] + red[448+t];
            const float M = (float)(Bq * Nq);
            float mv = ss / M;
            float var = qq / M - mv*mv;
            float mean = W_b[t] + mv;
            float sc = bn_g[t] * rsqrtf(var + 1e-5f);
            scale[t] = sc;
            shift[t] = bn_b[t] - mean*sc;
        }
        __syncthreads();

        const int TOT4 = Bq*Cq*Nq/4;
        const float4* wy4 = (const float4*)s_wy;
        const float4* x4  = (const float4*)x;
        float4* o4 = (float4*)out;
        for (int i4 = blockIdx.x*NTHR + t; i4 < TOT4; i4 += GRID*NTHR) {
            int c2 = (i4 / (Nq/4)) & 63;
            float sc = scale[c2], sh = shift[c2];
            float4 w = wy4[i4];
            float4 xv = x4[i4];
            float4 o;
            o.x = fmaf(w.x, sc, sh) + xv.x;
            o.y = fmaf(w.y, sc, sh) + xv.y;
            o.z = fmaf(w.z, sc, sh) + xv.z;
            o.w = fmaf(w.w, sc, sh) + xv.w;
            o4[i4] = o;
        }
    }
}

// ---------------- launch ----------------
extern "C" void kernel_launch(void* const* d_in, const int* in_sizes, int n_in,
                              void* d_out, int out_size) {
    const float* x     = (const float*)d_in[0];
    const float* g_w   = (const float*)d_in[1];
    const float* g_b   = (const float*)d_in[2];
    const float* th_w  = (const float*)d_in[3];
    const float* th_b  = (const float*)d_in[4];
    const float* ph_w  = (const float*)d_in[5];
    const float* ph_b  = (const float*)d_in[6];
    const float* cp_wt = (const float*)d_in[7];
    const float* cp_wp = (const float*)d_in[8];
    const float* W_w   = (const float*)d_in[9];
    const float* W_b   = (const float*)d_in[10];
    const float* bn_g  = (const float*)d_in[11];
    const float* bn_b  = (const float*)d_in[12];
    float* out = (float*)d_out;

    fused_nonlocal<<<GRID, NTHR>>>(x, g_w, g_b, th_w, th_b, ph_w, ph_b,
                                   cp_wt, cp_wp, W_w, W_b, bn_g, bn_b, out);
}

// round 4
// speedup vs baseline: 2.0468x; 1.2182x over previous
#include <cuda_runtime.h>

#define Bq 8
#define Cq 64
#define CIq 32
#define Nq 2304          // 48*48
#define NP1 2305
#define TILES 36         // 2304/64
#define NTILE (Bq*TILES) // 288
#define NCH 72           // suffix-scan chunks per batch
#define CHSZ 32
#define GRID 148
#define NTHR 512

// ---------------- scratch (__device__ globals; no allocations) ----------------
__device__ float s_a[Bq*Nq];
__device__ float s_b[Bq*Nq];
__device__ float s_gx[Bq*Nq*CIq];          // [b][n][i]
__device__ float s_keys[Bq*Nq];            // sorted b ascending (stable)
__device__ int   s_perm[Bq*Nq];
__device__ int   s_kstar[Bq*Nq];
__device__ float s_ctg[Bq*NCH*CIq];        // chunk totals (g)
__device__ float s_ctbg[Bq*NCH*CIq];       // chunk totals (b*g)
__device__ float s_Sg[Bq*NP1*CIq];         // inclusive suffix sums
__device__ float s_Sbg[Bq*NP1*CIq];
__device__ float s_wy[Bq*Cq*Nq];           // pre-BN output
__device__ float s_part[NTILE*Cq*2];       // per-tile (sum, sumsq)

// grid barrier state
__device__ unsigned g_bar = 0;
__device__ volatile unsigned g_gen = 0;

__device__ __forceinline__ void gsync() {
    __syncthreads();
    if (threadIdx.x == 0) {
        __threadfence();
        unsigned gen = g_gen;
        if (atomicAdd(&g_bar, 1u) == gridDim.x - 1) {
            g_bar = 0;
            __threadfence();
            g_gen = gen + 1;
        } else {
            while (g_gen == gen) { __nanosleep(64); }
        }
        __threadfence();
    }
    __syncthreads();
}

__global__ __launch_bounds__(NTHR, 1) void fused_nonlocal(
    const float* __restrict__ x,
    const float* __restrict__ g_w,  const float* __restrict__ g_b,
    const float* __restrict__ th_w, const float* __restrict__ th_b,
    const float* __restrict__ ph_w, const float* __restrict__ ph_b,
    const float* __restrict__ cp_wt, const float* __restrict__ cp_wp,
    const float* __restrict__ W_w,  const float* __restrict__ W_b,
    const float* __restrict__ bn_g, const float* __restrict__ bn_b,
    float* __restrict__ out)
{
    __shared__ __align__(16) unsigned char SM[43808];
    int t = threadIdx.x;

    // ================= P1: projections (gx, a, b) =================
    {
        float* xs  = (float*)SM;                      // [2][64*68]
        float* gws = (float*)(SM + 34816);            // 32*65
        float* was = (float*)(SM + 43136);            // 64
        float* wbs = (float*)(SM + 43392);            // 64
        float* cst = (float*)(SM + 43648);            // 2
        float* gbs = (float*)(SM + 43664);            // 32

        if (t < 64) {
            float sa = 0.f, sb = 0.f;
            #pragma unroll
            for (int i = 0; i < CIq; i++) {
                sa = fmaf(cp_wt[i], th_w[i*Cq + t], sa);
                sb = fmaf(cp_wp[i], ph_w[i*Cq + t], sb);
            }
            was[t] = sa; wbs[t] = sb;
        } else if (t == 64) {
            float ca = 0.f;
            #pragma unroll
            for (int i = 0; i < CIq; i++) ca = fmaf(cp_wt[i], th_b[i], ca);
            cst[0] = ca;
        } else if (t == 65) {
            float cb = 0.f;
            #pragma unroll
            for (int i = 0; i < CIq; i++) cb = fmaf(cp_wp[i], ph_b[i], cb);
            cst[1] = cb;
        }
        if (t >= 128 && t < 160) gbs[t - 128] = g_b[t - 128];
        for (int idx = t; idx < CIq*Cq; idx += NTHR)
            gws[(idx >> 6)*65 + (idx & 63)] = g_w[idx];
        __syncthreads();

        int half = t >> 8, tt = t & 255;
        int i = tt & 31, pg = tt >> 5;
        float* xsh = xs + half*(64*68);
        float cst0 = cst[0], cst1 = cst[1];
        float gb_i = gbs[i];

        for (int pair = blockIdx.x; pair < NTILE/2; pair += GRID) {
            int tile = pair*2 + half;
            int b = tile / TILES, n0 = (tile % TILES)*64;
            float4* xs4 = (float4*)xsh;
            const float4* xg = (const float4*)x;
            for (int idx = tt; idx < Cq*16; idx += 256) {
                int c = idx >> 4, q = idx & 15;
                xs4[c*17 + q] = xg[(((b*Cq + c)*Nq + n0) >> 2) + q];
            }
            __syncthreads();

            float acc[8];
            #pragma unroll
            for (int p = 0; p < 8; p++) acc[p] = gb_i;
            #pragma unroll
            for (int c = 0; c < Cq; c++) {
                float w = gws[i*65 + c];
                float4 xa = *(const float4*)&xsh[c*68 + pg*8];
                float4 xb = *(const float4*)&xsh[c*68 + pg*8 + 4];
                acc[0] = fmaf(w, xa.x, acc[0]); acc[1] = fmaf(w, xa.y, acc[1]);
                acc[2] = fmaf(w, xa.z, acc[2]); acc[3] = fmaf(w, xa.w, acc[3]);
                acc[4] = fmaf(w, xb.x, acc[4]); acc[5] = fmaf(w, xb.y, acc[5]);
                acc[6] = fmaf(w, xb.z, acc[6]); acc[7] = fmaf(w, xb.w, acc[7]);
            }
            #pragma unroll
            for (int p = 0; p < 8; p++)
                s_gx[(b*Nq + n0 + pg*8 + p)*CIq + i] = acc[p];

            if (tt < 64) {
                float aa = cst0, bb = cst1;
                #pragma unroll
                for (int c = 0; c < Cq; c++) {
                    float xv = xsh[c*68 + tt];
                    aa = fmaf(was[c], xv, aa);
                    bb = fmaf(wbs[c], xv, bb);
                }
                s_a[b*Nq + n0 + tt] = aa;
                s_b[b*Nq + n0 + tt] = bb;
            }
            __syncthreads();
        }
    }
    gsync();

    // ================= P2: stable rank-by-counting =================
    {
        unsigned* osb = (unsigned*)SM;                // 2304
        unsigned* cnt = (unsigned*)(SM + Nq*4);       // 8*128

        for (int item = blockIdx.x; item < 144; item += GRID) {
            int b = item / 18, slice = item % 18;
            int pos_base = slice * 128;
            for (int idx = t; idx < Nq; idx += NTHR) {
                int iv = __float_as_int(s_b[b*Nq + idx]);
                osb[idx] = (unsigned)(iv ^ ((iv >> 31) | 0x80000000));
            }
            __syncthreads();

            int g = t & 63, s = t >> 6;               // s: 0..7
            int m0 = pos_base + g, m1 = m0 + 64;
            unsigned om0 = osb[m0], om1 = osb[m1];
            int jlo = s * 288, jhi = jlo + 288;
            unsigned cnt0 = 0, cnt1 = 0;
            const uint4* o4 = (const uint4*)osb;

            auto count_range = [&](int lo, int hi, unsigned th0, unsigned th1) {
                int v0 = min((lo + 3) & ~3, hi);
                int v1 = max(hi & ~3, v0);
                for (int j = lo; j < v0; j++) {
                    unsigned v = osb[j]; cnt0 += (v < th0); cnt1 += (v < th1);
                }
                for (int q = v0 >> 2; q < (v1 >> 2); q++) {
                    uint4 v = o4[q];
                    cnt0 += (v.x < th0) + (v.y < th0) + (v.z < th0) + (v.w < th0);
                    cnt1 += (v.x < th1) + (v.y < th1) + (v.z < th1) + (v.w < th1);
                }
                for (int j = v1; j < hi; j++) {
                    unsigned v = osb[j]; cnt0 += (v < th0); cnt1 += (v < th1);
                }
            };
            int A  = min(max(m0, jlo), jhi);
            int Bp = min(max(m1, A), jhi);
            count_range(jlo, A,  om0 + 1u, om1 + 1u);
            count_range(A,   Bp, om0,      om1 + 1u);
            count_range(Bp,  jhi, om0,     om1);

            cnt[s*128 + g]      = cnt0;
            cnt[s*128 + 64 + g] = cnt1;
            __syncthreads();

            if (t < 128) {
                int pos = pos_base + t;
                unsigned rank = 0;
                #pragma unroll
                for (int ss = 0; ss < 8; ss++) rank += cnt[ss*128 + t];
                s_keys[b*Nq + rank] = s_b[b*Nq + pos];
                s_perm[b*Nq + rank] = pos;
            }
            __syncthreads();
        }
    }
    gsync();

    // ================= P3: chunk totals + per-position k* =================
    {
        float* keys_sm = (float*)SM;                  // 2304
        for (int item = blockIdx.x; item < 144; item += GRID) {
            int b = item / 18, sub = item % 18;
            for (int idx = t; idx < Nq; idx += NTHR)
                keys_sm[idx] = s_keys[b*Nq + idx];
            __syncthreads();

            int w = t >> 5, lane = t & 31;
            if (w < 4) {
                int chunk = sub*4 + w;
                int k0 = chunk * CHSZ;
                const float* gxb = s_gx + b*Nq*CIq;
                const int* permb = s_perm + b*Nq;
                float ag = 0.f, abg = 0.f;
                #pragma unroll
                for (int k = k0; k < k0 + CHSZ; k++) {
                    int m = permb[k];
                    float gg = gxb[m*CIq + lane];
                    ag += gg;
                    abg = fmaf(keys_sm[k], gg, abg);
                }
                s_ctg [(b*NCH + chunk)*CIq + lane] = ag;
                s_ctbg[(b*NCH + chunk)*CIq + lane] = abg;
            } else if (w < 8) {
                int pos = sub*128 + (t - 128);
                float thr = -s_a[b*Nq + pos];
                int lo = 0, hi = Nq;
                while (lo < hi) {
                    int mid = (lo + hi) >> 1;
                    if (keys_sm[mid] <= thr) lo = mid + 1; else hi = mid;
                }
                s_kstar[b*Nq + pos] = lo;
            }
            __syncthreads();
        }
    }
    gsync();

    // ================= P4: suffix sums (2 warps per chunk) =================
    {
        int w16 = t >> 5, lane = t & 31;
        for (int item = blockIdx.x; item < 72; item += GRID) {
            int b = item / 9, cb = item % 9;
            int chunk = cb*8 + (w16 >> 1), hc = w16 & 1;
            float rg = 0.f, rbg = 0.f;
            #pragma unroll 4
            for (int ch = chunk + 1; ch < NCH; ch++) {
                rg  += s_ctg [(b*NCH + ch)*CIq + lane];
                rbg += s_ctbg[(b*NCH + ch)*CIq + lane];
            }
            const float* gxb = s_gx + b*Nq*CIq;
            const int* permb = s_perm + b*Nq;
            const float* keyb = s_keys + b*Nq;
            int k0 = chunk * CHSZ;
            if (hc == 0) {
                #pragma unroll
                for (int k = k0 + 31; k >= k0 + 16; k--) {
                    int m = permb[k];
                    float gg = gxb[m*CIq + lane];
                    rg += gg;
                    rbg = fmaf(keyb[k], gg, rbg);
                }
            }
            int kstart = k0 + hc*16;
            float ag = rg, abg = rbg;
            #pragma unroll
            for (int k = kstart + 15; k >= kstart; k--) {
                int m = permb[k];
                float gg = gxb[m*CIq + lane];
                ag += gg;
                abg = fmaf(keyb[k], gg, abg);
                s_Sg [(b*NP1 + k)*CIq + lane] = ag;
                s_Sbg[(b*NP1 + k)*CIq + lane] = abg;
            }
            if (cb == 0 && w16 == 0) {
                s_Sg [(b*NP1 + Nq)*CIq + lane] = 0.f;
                s_Sbg[(b*NP1 + Nq)*CIq + lane] = 0.f;
            }
        }
    }
    gsync();

    // ================= P5: y lookup + W projection + BN partials =================
    {
        float* ws   = (float*)SM;                     // 64*33
        float* ys   = (float*)(SM + 8448);            // [2][64*36]
        float* a_sm = (float*)(SM + 26880);           // [2][64]
        int*   k_sm = (int*)(SM + 27392);             // [2][64]
        float* psum = (float*)(SM + 27904);           // [2][4*64]
        float* psq  = (float*)(SM + 29952);           // [2][4*64]

        for (int idx = t; idx < Cq*CIq; idx += NTHR)
            ws[(idx >> 5)*33 + (idx & 31)] = W_w[idx];
        __syncthreads();

        int half = t >> 8, tt = t & 255;
        float* ysh = ys + half*(64*36);
        int c = tt & 63, sub = tt >> 6;
        float wreg[CIq];
        #pragma unroll
        for (int i = 0; i < CIq; i++) wreg[i] = ws[c*33 + i];
        float wbc = W_b[c];

        for (int pair = blockIdx.x; pair < NTILE/2; pair += GRID) {
            int tile = pair*2 + half;
            int b = tile / TILES, n0 = (tile % TILES)*64;
            if (tt < 64) {
                a_sm[half*64 + tt] = s_a[b*Nq + n0 + tt];
                k_sm[half*64 + tt] = s_kstar[b*Nq + n0 + tt];
            }
            __syncthreads();

            {
                int i = tt & 31, pg = tt >> 5;
                #pragma unroll
                for (int p = 0; p < 8; p++) {
                    int pos = pg*8 + p;
                    int k = k_sm[half*64 + pos];
                    float sg  = s_Sg [(b*NP1 + k)*CIq + i];
                    float sbg = s_Sbg[(b*NP1 + k)*CIq + i];
                    ysh[pos*36 + i] = fmaf(a_sm[half*64 + pos], sg, sbg) * (1.0f / (float)Nq);
                }
            }
            __syncthreads();

            {
                float ls = 0.f, ls2 = 0.f;
                float* wyrow = s_wy + (b*Cq + c)*Nq + n0 + sub*16;
                #pragma unroll
                for (int q4 = 0; q4 < 4; q4++) {
                    float av[4];
                    #pragma unroll
                    for (int u = 0; u < 4; u++) {
                        int pos = sub*16 + q4*4 + u;
                        const float4* yv = (const float4*)&ysh[pos*36];
                        float acc = 0.f;
                        #pragma unroll
                        for (int i4 = 0; i4 < CIq/4; i4++) {
                            float4 v = yv[i4];
                            acc = fmaf(wreg[i4*4+0], v.x, acc);
                            acc = fmaf(wreg[i4*4+1], v.y, acc);
                            acc = fmaf(wreg[i4*4+2], v.z, acc);
                            acc = fmaf(wreg[i4*4+3], v.w, acc);
                        }
                        av[u] = acc;
                        ls += acc; ls2 = fmaf(acc, acc, ls2);
                    }
                    float4 o;
                    o.x = av[0] + wbc; o.y = av[1] + wbc;
                    o.z = av[2] + wbc; o.w = av[3] + wbc;
                    *(float4*)(wyrow + q4*4) = o;
                }
                psum[half*256 + sub*64 + c] = ls;
                psq [half*256 + sub*64 + c] = ls2;
            }
            __syncthreads();

            if (tt < 64) {
                int o = half*256;
                float s  = psum[o+tt] + psum[o+64+tt] + psum[o+128+tt] + psum[o+192+tt];
                float s2 = psq[o+tt]  + psq[o+64+tt]  + psq[o+128+tt]  + psq[o+192+tt];
                s_part[(tile*Cq + tt)*2 + 0] = s;
                s_part[(tile*Cq + tt)*2 + 1] = s2;
            }
            __syncthreads();
        }
    }
    gsync();

    // ================= P6: BN stats (redundant per block) + final =================
    {
        float* red   = (float*)SM;            // [8][64] sums + [8][64] sumsq
        float* scale = (float*)(SM + 4096);   // 64
        float* shift = (float*)(SM + 4352);   // 64

        int c = t & 63, r = t >> 6;           // r: 0..7
        float s = 0.f, s2 = 0.f;
        for (int blk = r; blk < NTILE; blk += 8) {
            s  += s_part[(blk*Cq + c)*2 + 0];
            s2 += s_part[(blk*Cq + c)*2 + 1];
        }
        red[r*64 + c] = s;
        red[512 + r*64 + c] = s2;
        __syncthreads();
        if (t < 64) {
            float ss = 0.f, qq = 0.f;
            #pragma unroll
            for (int rr = 0; rr < 8; rr++) {
                ss += red[rr*64 + t];
                qq += red[512 + rr*64 + t];
            }
            const float M = (float)(Bq * Nq);
            float mv = ss / M;
            float var = qq / M - mv*mv;
            float mean = W_b[t] + mv;
            float sc = bn_g[t] * rsqrtf(var + 1e-5f);
            scale[t] = sc;
            shift[t] = bn_b[t] - mean*sc;
        }
        __syncthreads();

        const int TOT4 = Bq*Cq*Nq/4;
        const float4* wy4 = (const float4*)s_wy;
        const float4* x4  = (const float4*)x;
        float4* o4 = (float4*)out;
        for (int i4 = blockIdx.x*NTHR + t; i4 < TOT4; i4 += GRID*NTHR) {
            int c2 = (i4 / (Nq/4)) & 63;
            float sc = scale[c2], sh = shift[c2];
            float4 w = wy4[i4];
            float4 xv = x4[i4];
            float4 o;
            o.x = fmaf(w.x, sc, sh) + xv.x;
            o.y = fmaf(w.y, sc, sh) + xv.y;
            o.z = fmaf(w.z, sc, sh) + xv.z;
            o.w = fmaf(w.w, sc, sh) + xv.w;
            o4[i4] = o;
        }
    }
}

// ---------------- launch ----------------
extern "C" void kernel_launch(void* const* d_in, const int* in_sizes, int n_in,
                              void* d_out, int out_size) {
    const float* x     = (const float*)d_in[0];
    const float* g_w   = (const float*)d_in[1];
    const float* g_b   = (const float*)d_in[2];
    const float* th_w  = (const float*)d_in[3];
    const float* th_b  = (const float*)d_in[4];
    const float* ph_w  = (const float*)d_in[5];
    const float* ph_b  = (const float*)d_in[6];
    const float* cp_wt = (const float*)d_in[7];
    const float* cp_wp = (const float*)d_in[8];
    const float* W_w   = (const float*)d_in[9];
    const float* W_b   = (const float*)d_in[10];
    const float* bn_g  = (const float*)d_in[11];
    const float* bn_b  = (const float*)d_in[12];
    float* out = (float*)d_out;

    fused_nonlocal<<<GRID, NTHR>>>(x, g_w, g_b, th_w, th_b, ph_w, ph_b,
                                   cp_wt, cp_wp, W_w, W_b, bn_g, bn_b, out);
}